// round 6
// baseline (speedup 1.0000x reference)
#include <cuda_runtime.h>
#include <math.h>
#include <stdint.h>

#define D       256
#define K       8
#define FULLM   0xffffffffu

#define CTAS    296          // 2 CTAs/SM * 148
#define TPB     128
#define WPB     4
#define TOTW    (CTAS * WPB)

// k_assign tiles: 8 rows x 256 cols (full rows), pitch 1040B, double-buffered
#define AT_ROWS   8
#define AT_PITCH  1040
#define AT_BYTES  (AT_ROWS * AT_PITCH)       // 8320
// k_loss tiles: 32 rows x 64-col span, pitch 272B, double-buffered
#define LT_PITCH  272
#define LT_BYTES  (32 * LT_PITCH)            // 8704

// dynamic smem maps
#define A_PROTO_OFF 0                         // q-blocked protos: 32*68 floats = 8704B
#define A_TILE_OFF  8704
#define A_ACC_OFF   (8704 + 8 * AT_BYTES)     // 75264
#define A_SMEM      (A_ACC_OFF + WPB * 8192)  // 108032

#define L_PROTO_OFF 0                         // plain protos 8192B
#define L_TILE_OFF  8192
#define L_SMEM      (8192 + 8 * LT_BYTES)     // 77824

typedef unsigned long long u64;

// ---- device scratch ----
__device__ float g_part_sums[CTAS * K * D];
__device__ int   g_part_counts[CTAS * K];
__device__ float g_mid[8 * K * D];
__device__ float g_part_loss[CTAS];
__device__ float g_protos_new[K * D];

// ---------------- helpers ----------------
__device__ __forceinline__ u64 pk2(float lo, float hi) {
    u64 r; asm("mov.b64 %0, {%1, %2};" : "=l"(r) : "f"(lo), "f"(hi)); return r;
}
__device__ __forceinline__ float hadd2(u64 v) {
    float lo, hi; asm("mov.b64 {%0, %1}, %2;" : "=f"(lo), "=f"(hi) : "l"(v));
    return lo + hi;
}
__device__ __forceinline__ u64 ffma2(u64 a, u64 b, u64 c) {
    u64 d; asm("fma.rn.f32x2 %0, %1, %2, %3;" : "=l"(d) : "l"(a), "l"(b), "l"(c)); return d;
}
__device__ __forceinline__ void cp16(uint32_t s, const void* g) {
    asm volatile("cp.async.ca.shared.global [%0], [%1], 16;" :: "r"(s), "l"(g));
}
#define CP_COMMIT() asm volatile("cp.async.commit_group;" ::: "memory")
#define CP_WAIT1()  asm volatile("cp.async.wait_group 1;" ::: "memory")

__device__ __forceinline__ float warp_sum(float v) {
    v += __shfl_xor_sync(FULLM, v, 16);
    v += __shfl_xor_sync(FULLM, v, 8);
    v += __shfl_xor_sync(FULLM, v, 4);
    v += __shfl_xor_sync(FULLM, v, 2);
    v += __shfl_xor_sync(FULLM, v, 1);
    return v;
}

// ============================================================================
// Kernel 1: assignment + per-cluster normalized sums.
// 8-row full-row tiles per warp, 4 lanes per row, double-buffered cp.async.
// ============================================================================
extern __shared__ char dsm[];

__global__ void __launch_bounds__(TPB, 2)
k_assign(const float* __restrict__ src, const float* __restrict__ protos, int N)
{
    const int tid  = threadIdx.x;
    const int lane = tid & 31;
    const int warp = tid >> 5;

    float* s_proto = (float*)(dsm + A_PROTO_OFF);          // q-blocked [k][q][68]
    float* s_accw  = (float*)(dsm + A_ACC_OFF) + warp * (K * D);
    float* s_accb  = (float*)(dsm + A_ACC_OFF);
    __shared__ int s_icnt[WPB * K];

    for (int e = tid; e < K * D; e += TPB) {
        int k = e >> 8, col = e & 255, q = col >> 6, c = col & 63;
        s_proto[(k * 4 + q) * 68 + c] = protos[e];
    }
    for (int e = tid; e < WPB * K * D; e += TPB) s_accb[e] = 0.0f;
    __syncthreads();

    const int wgid   = blockIdx.x * WPB + warp;
    const int ntiles = (N + AT_ROWS - 1) / AT_ROWS;

    char* tbuf[2] = { dsm + A_TILE_OFF + (warp * 2 + 0) * AT_BYTES,
                      dsm + A_TILE_OFF + (warp * 2 + 1) * AT_BYTES };
    uint32_t sb[2] = { (uint32_t)__cvta_generic_to_shared(tbuf[0]),
                       (uint32_t)__cvta_generic_to_shared(tbuf[1]) };

    auto load_tile = [&](int t, uint32_t sbase) {
        const int row0 = t * AT_ROWS;
#pragma unroll
        for (int i = 0; i < 16; i++) {
            int idx = i * 32 + lane;
            int r = idx >> 6, c4 = idx & 63;
            int row = min(row0 + r, N - 1);
            cp16(sbase + r * AT_PITCH + c4 * 16, src + (size_t)row * D + c4 * 4);
        }
    };

    const int r = lane & 7, q = lane >> 3;
    int cnt = 0;

    int t_cur = wgid;
    if (t_cur < ntiles) load_tile(t_cur, sb[0]);
    CP_COMMIT();
    int t_pre = t_cur + TOTW;
    if (t_pre < ntiles) load_tile(t_pre, sb[1]);
    CP_COMMIT();
    int par = 0;

    while (t_cur < ntiles) {
        CP_WAIT1();
        __syncwarp();
        const char* tb = tbuf[par];

        // ---- compute 9 packed sums over this lane's quarter-row ----
        u64 acc[9];
#pragma unroll
        for (int k = 0; k < 9; k++) acc[k] = 0ull;

        const ulonglong2* rowp = (const ulonglong2*)(tb + r * AT_PITCH + q * 256);
        const ulonglong2* prp  = (const ulonglong2*)((const char*)s_proto + q * 272);
#pragma unroll
        for (int c = 0; c < 16; c++) {
            const ulonglong2 R = rowp[c];
            acc[8] = ffma2(R.x, R.x, acc[8]);
            acc[8] = ffma2(R.y, R.y, acc[8]);
#pragma unroll
            for (int k = 0; k < K; k++) {
                const ulonglong2 P = prp[k * 68 + c];
                acc[k] = ffma2(R.x, P.x, acc[k]);
                acc[k] = ffma2(R.y, P.y, acc[k]);
            }
        }

        float v[9];
#pragma unroll
        for (int k = 0; k < 9; k++) {
            float s = hadd2(acc[k]);
            s += __shfl_xor_sync(FULLM, s, 8);
            s += __shfl_xor_sync(FULLM, s, 16);
            v[k] = s;
        }
        const float inv = rsqrtf(fmaxf(v[8], 1e-24f));

        // thread-local argmax, first-max tiebreak
        float bv = v[0];
        int   bk = 0;
#pragma unroll
        for (int k = 1; k < K; k++) {
            if (v[k] > bv) { bv = v[k]; bk = k; }
        }

        // ---- accumulate: warp cooperates row-by-row from smem tile ----
#pragma unroll
        for (int r2 = 0; r2 < AT_ROWS; r2++) {
            int row = t_cur * AT_ROWS + r2;
            if (row < N) {
                int   bkr  = __shfl_sync(FULLM, bk, r2);
                float invr = __shfl_sync(FULLM, inv, r2);
                cnt += (bkr == (lane & 7));
                const u64 iv = pk2(invr, invr);
                const ulonglong2* rp2 = (const ulonglong2*)(tb + r2 * AT_PITCH);
                ulonglong2 R0 = rp2[lane];
                ulonglong2 R1 = rp2[32 + lane];
                ulonglong2* a0 = (ulonglong2*)(s_accw + bkr * D) + lane;
                ulonglong2 c0 = a0[0];
                c0.x = ffma2(R0.x, iv, c0.x);
                c0.y = ffma2(R0.y, iv, c0.y);
                a0[0] = c0;
                ulonglong2 c1 = a0[32];
                c1.x = ffma2(R1.x, iv, c1.x);
                c1.y = ffma2(R1.y, iv, c1.y);
                a0[32] = c1;
            }
        }
        __syncwarp();

        int t_n = t_pre + TOTW;
        if (t_n < ntiles) load_tile(t_n, sb[par]);
        CP_COMMIT();
        t_cur = t_pre; t_pre = t_n; par ^= 1;
    }

    // counts: lane tracked cluster (lane & 7); fold lanes l, l+8, l+16, l+24
    cnt += __shfl_xor_sync(FULLM, cnt, 8);
    cnt += __shfl_xor_sync(FULLM, cnt, 16);
    if (lane < K) s_icnt[warp * K + lane] = cnt;
    __syncthreads();

    for (int e = tid; e < K * D; e += TPB) {
        float s = s_accb[e] + s_accb[e + K * D] + s_accb[e + 2 * K * D] + s_accb[e + 3 * K * D];
        g_part_sums[blockIdx.x * (K * D) + e] = s;
    }
    if (tid < K) {
        int c = 0;
#pragma unroll
        for (int w = 0; w < WPB; w++) c += s_icnt[w * K + tid];
        g_part_counts[blockIdx.x * K + tid] = c;
    }
}

// ============================================================================
// Kernel 2: reduce CTAS partial blocks -> 8 mid blocks
// ============================================================================
#define RCHUNK 37   // ceil(296 / 8)
__global__ void k_reduce1()
{
    const int be = blockIdx.x & 7;
    const int bb = blockIdx.x >> 3;
    const int e  = be * 256 + threadIdx.x;
    float s = 0.0f;
    const int b0 = bb * RCHUNK;
    const int b1 = min(b0 + RCHUNK, CTAS);
    for (int b = b0; b < b1; b++) s += g_part_sums[b * (K * D) + e];
    g_mid[bb * (K * D) + e] = s;
}

// ============================================================================
// Kernel 3: final reduce + prototype EMA update + renormalize (1 block)
// ============================================================================
__global__ void k_update(const float* __restrict__ protos)
{
    __shared__ float s_sums[K * D];
    __shared__ int   s_cnt[K];

    const int tid  = threadIdx.x;
    const int lane = tid & 31;
    const int warp = tid >> 5;

    for (int e = tid; e < K * D; e += 256) {
        float s = 0.0f;
#pragma unroll
        for (int m = 0; m < 8; m++) s += g_mid[m * (K * D) + e];
        s_sums[e] = s;
    }
    {
        int c = 0;
        for (int b = lane; b < CTAS; b += 32) c += g_part_counts[b * K + warp];
        c = __reduce_add_sync(FULLM, c);
        if (lane == 0) s_cnt[warp] = c;
    }
    __syncthreads();

    const int k = warp;   // 8 warps = 8 clusters
    const float4* s4 = (const float4*)s_sums;
    float4 s1 = s4[k * 64 + lane];
    float4 s2 = s4[k * 64 + 32 + lane];

    const int   c = s_cnt[k];
    const float rr = 1.0f / fmaxf((float)c, 1.0f);
    float4 m1 = make_float4(s1.x*rr, s1.y*rr, s1.z*rr, s1.w*rr);
    float4 m2 = make_float4(s2.x*rr, s2.y*rr, s2.z*rr, s2.w*rr);

    float ss = m1.x*m1.x + m1.y*m1.y + m1.z*m1.z + m1.w*m1.w
             + m2.x*m2.x + m2.y*m2.y + m2.z*m2.z + m2.w*m2.w;
    ss = warp_sum(ss);
    const float inv = 1.0f / fmaxf(sqrtf(ss), 1e-12f);

    const float4* p4 = (const float4*)protos;
    const float4 p1 = p4[k * 64 + lane];
    const float4 p2 = p4[k * 64 + 32 + lane];

    float4 u1, u2;
    if (c > 0) {
        u1 = make_float4(0.9f*p1.x + 0.1f*m1.x*inv, 0.9f*p1.y + 0.1f*m1.y*inv,
                         0.9f*p1.z + 0.1f*m1.z*inv, 0.9f*p1.w + 0.1f*m1.w*inv);
        u2 = make_float4(0.9f*p2.x + 0.1f*m2.x*inv, 0.9f*p2.y + 0.1f*m2.y*inv,
                         0.9f*p2.z + 0.1f*m2.z*inv, 0.9f*p2.w + 0.1f*m2.w*inv);
    } else {
        u1 = p1; u2 = p2;
    }

    float ss2 = u1.x*u1.x + u1.y*u1.y + u1.z*u1.z + u1.w*u1.w
              + u2.x*u2.x + u2.y*u2.y + u2.z*u2.z + u2.w*u2.w;
    ss2 = warp_sum(ss2);
    const float inv2 = 1.0f / fmaxf(sqrtf(ss2), 1e-12f);

    float4* o4 = (float4*)g_protos_new;
    o4[k * 64 + lane]      = make_float4(u1.x*inv2, u1.y*inv2, u1.z*inv2, u1.w*inv2);
    o4[k * 64 + 32 + lane] = make_float4(u2.x*inv2, u2.y*inv2, u2.z*inv2, u2.w*inv2);
}

// ============================================================================
// Kernel 4: target loss — lane-per-row, 32-row x 64-col span tiles, zero shuffles
// ============================================================================
__global__ void __launch_bounds__(TPB, 2)
k_loss(const float* __restrict__ tgt, int N)
{
    const int tid  = threadIdx.x;
    const int lane = tid & 31;
    const int warp = tid >> 5;

    float* s_proto = (float*)(dsm + L_PROTO_OFF);   // plain [k][256]
    __shared__ float s_l[WPB];

    for (int e = tid; e < K * D; e += TPB) s_proto[e] = g_protos_new[e];
    __syncthreads();

    const int wgid   = blockIdx.x * WPB + warp;
    const int ntiles = (N + 31) / 32;

    char* tbuf[2] = { dsm + L_TILE_OFF + (warp * 2 + 0) * LT_BYTES,
                      dsm + L_TILE_OFF + (warp * 2 + 1) * LT_BYTES };
    uint32_t sb[2] = { (uint32_t)__cvta_generic_to_shared(tbuf[0]),
                       (uint32_t)__cvta_generic_to_shared(tbuf[1]) };

    auto load_span = [&](int t, int sp, uint32_t sbase) {
        const int row0 = t * 32;
#pragma unroll
        for (int i = 0; i < 16; i++) {
            int idx = i * 32 + lane;
            int r = idx >> 4, c4 = idx & 15;
            int row = min(row0 + r, N - 1);
            cp16(sbase + r * LT_PITCH + c4 * 16, tgt + (size_t)row * D + sp * 64 + c4 * 4);
        }
    };

    float lsum = 0.0f;
    u64 acc[9];
#pragma unroll
    for (int k = 0; k < 9; k++) acc[k] = 0ull;

    int t_cur = wgid, sp_cur = 0;
    if (t_cur < ntiles) load_span(t_cur, sp_cur, sb[0]);
    CP_COMMIT();
    int t_pre = t_cur, sp_pre = 1;
    if (t_pre < ntiles) load_span(t_pre, sp_pre, sb[1]);
    CP_COMMIT();
    int par = 0;

    while (t_cur < ntiles) {
        CP_WAIT1();
        __syncwarp();
        const char* tb = tbuf[par];

        const ulonglong2* rowp = (const ulonglong2*)(tb + lane * LT_PITCH);
        const ulonglong2* prp  = (const ulonglong2*)((const char*)s_proto + sp_cur * 256);
#pragma unroll
        for (int c = 0; c < 16; c++) {
            const ulonglong2 R = rowp[c];
            acc[8] = ffma2(R.x, R.x, acc[8]);
            acc[8] = ffma2(R.y, R.y, acc[8]);
#pragma unroll
            for (int k = 0; k < K; k++) {
                const ulonglong2 P = prp[k * 64 + c];
                acc[k] = ffma2(R.x, P.x, acc[k]);
                acc[k] = ffma2(R.y, P.y, acc[k]);
            }
        }

        if (sp_cur == 3) {
            float v0 = hadd2(acc[0]), v1 = hadd2(acc[1]);
            float v2 = hadd2(acc[2]), v3 = hadd2(acc[3]);
            float v4 = hadd2(acc[4]), v5 = hadd2(acc[5]);
            float v6 = hadd2(acc[6]), v7 = hadd2(acc[7]);
            float ss = hadd2(acc[8]);
            float m = fmaxf(fmaxf(fmaxf(v0, v1), fmaxf(v2, v3)),
                            fmaxf(fmaxf(v4, v5), fmaxf(v6, v7)));
            int row = t_cur * 32 + lane;
            if (row < N) lsum += m * rsqrtf(fmaxf(ss, 1e-24f));
#pragma unroll
            for (int k = 0; k < 9; k++) acc[k] = 0ull;
        }
        __syncwarp();

        int t_n = t_pre, sp_n = sp_pre + 1;
        if (sp_n == 4) { sp_n = 0; t_n += TOTW; }
        if (t_n < ntiles) load_span(t_n, sp_n, sb[par]);
        CP_COMMIT();
        t_cur = t_pre; sp_cur = sp_pre;
        t_pre = t_n;   sp_pre = sp_n;
        par ^= 1;
    }

    lsum = warp_sum(lsum);
    if (lane == 0) s_l[warp] = lsum;
    __syncthreads();
    if (tid == 0) {
        float s = 0.0f;
#pragma unroll
        for (int w = 0; w < WPB; w++) s += s_l[w];
        g_part_loss[blockIdx.x] = s;
    }
}

// ============================================================================
// Kernel 5: final mean:  out = 1 - (sum of max cos) / Nt
// ============================================================================
__global__ void k_final(float* __restrict__ out, int Nt)
{
    __shared__ float sw[16];
    const int tid  = threadIdx.x;
    const int lane = tid & 31;
    const int warp = tid >> 5;

    float v = (tid < CTAS) ? g_part_loss[tid] : 0.0f;
    v = warp_sum(v);
    if (lane == 0) sw[warp] = v;
    __syncthreads();
    if (tid == 0) {
        float s = 0.0f;
#pragma unroll
        for (int w = 0; w < 16; w++) s += sw[w];
        out[0] = 1.0f - s / (float)Nt;
    }
}

// ============================================================================
extern "C" void kernel_launch(void* const* d_in, const int* in_sizes, int n_in,
                              void* d_out, int out_size)
{
    const float* src    = (const float*)d_in[0];
    const float* tgt    = (const float*)d_in[1];
    const float* protos = (const float*)d_in[2];
    float* out = (float*)d_out;

    const int Ns = in_sizes[0] / D;
    const int Nt = in_sizes[1] / D;

    cudaFuncSetAttribute(k_assign, cudaFuncAttributeMaxDynamicSharedMemorySize, A_SMEM);
    cudaFuncSetAttribute(k_loss,   cudaFuncAttributeMaxDynamicSharedMemorySize, L_SMEM);

    k_assign<<<CTAS, TPB, A_SMEM>>>(src, protos, Ns);
    k_reduce1<<<64, 256>>>();
    k_update<<<1, 256>>>(protos);
    k_loss<<<CTAS, TPB, L_SMEM>>>(tgt, Nt);
    k_final<<<1, 512>>>(out, Nt);
}

// round 7
// speedup vs baseline: 1.3759x; 1.3759x over previous
#include <cuda_runtime.h>
#include <math.h>
#include <stdint.h>

#define D       256
#define K       8
#define FULLM   0xffffffffu

// both big kernels: 64 threads (2 warps), 7 CTAs/SM
#define TPB     64
#define WPB     2
#define CTAS    1036         // 7 * 148
#define TOTW    (CTAS * WPB)

typedef unsigned long long u64;

// ---- device scratch (no allocations allowed) ----
__device__ float g_part_sums[CTAS * K * D];   // per-block per-cluster sums (8.5MB)
__device__ int   g_part_counts[CTAS * K];
__device__ float g_mid[8 * K * D];            // stage-2 partials
__device__ float g_part_loss[CTAS];
__device__ float g_protos_new[K * D];

// ---------------- f32x2 packed helpers ----------------
__device__ __forceinline__ u64 pk2(float lo, float hi) {
    u64 r; asm("mov.b64 %0, {%1, %2};" : "=l"(r) : "f"(lo), "f"(hi)); return r;
}
__device__ __forceinline__ float hadd2(u64 v) {
    float lo, hi; asm("mov.b64 {%0, %1}, %2;" : "=f"(lo), "=f"(hi) : "l"(v));
    return lo + hi;
}
__device__ __forceinline__ u64 mul2(u64 a, u64 b) {
    u64 d; asm("mul.rn.f32x2 %0, %1, %2;" : "=l"(d) : "l"(a), "l"(b)); return d;
}
__device__ __forceinline__ u64 ffma2(u64 a, u64 b, u64 c) {
    u64 d; asm("fma.rn.f32x2 %0, %1, %2, %3;" : "=l"(d) : "l"(a), "l"(b), "l"(c)); return d;
}

__device__ __forceinline__ float warp_sum(float v) {
    v += __shfl_xor_sync(FULLM, v, 16);
    v += __shfl_xor_sync(FULLM, v, 8);
    v += __shfl_xor_sync(FULLM, v, 4);
    v += __shfl_xor_sync(FULLM, v, 2);
    v += __shfl_xor_sync(FULLM, v, 1);
    return v;
}

// Folded 8-value warp reduction: 9 shuffles. On return, lane l holds the
// full 32-lane sum of value index k(l) = (l >> 2) & 7.
__device__ __forceinline__ float fold8(const float* v, int lane) {
    float v0, v1, v2, v3;
    {
        bool hi = (lane & 16) != 0;
        float k0 = hi ? v[4] : v[0], k1 = hi ? v[5] : v[1];
        float k2 = hi ? v[6] : v[2], k3 = hi ? v[7] : v[3];
        float s0 = hi ? v[0] : v[4], s1 = hi ? v[1] : v[5];
        float s2 = hi ? v[2] : v[6], s3 = hi ? v[3] : v[7];
        v0 = k0 + __shfl_xor_sync(FULLM, s0, 16);
        v1 = k1 + __shfl_xor_sync(FULLM, s1, 16);
        v2 = k2 + __shfl_xor_sync(FULLM, s2, 16);
        v3 = k3 + __shfl_xor_sync(FULLM, s3, 16);
    }
    {
        bool hi = (lane & 8) != 0;
        float k0 = hi ? v2 : v0, k1 = hi ? v3 : v1;
        float s0 = hi ? v0 : v2, s1 = hi ? v1 : v3;
        v0 = k0 + __shfl_xor_sync(FULLM, s0, 8);
        v1 = k1 + __shfl_xor_sync(FULLM, s1, 8);
    }
    {
        bool hi = (lane & 4) != 0;
        float k0 = hi ? v1 : v0;
        float s0 = hi ? v0 : v1;
        v0 = k0 + __shfl_xor_sync(FULLM, s0, 4);
    }
    v0 += __shfl_xor_sync(FULLM, v0, 2);
    v0 += __shfl_xor_sync(FULLM, v0, 1);
    return v0;
}

// per-row core: packed dots vs 8 prototypes + self norm (no reductions)
__device__ __forceinline__ void dots8(const ulonglong2& A, const ulonglong2& B,
                                      const ulonglong2* PA, const ulonglong2* PB,
                                      float* v, float& ssout)
{
    u64 ss2 = mul2(A.x, A.x);
    ss2 = ffma2(A.y, A.y, ss2);
    ss2 = ffma2(B.x, B.x, ss2);
    ss2 = ffma2(B.y, B.y, ss2);
#pragma unroll
    for (int k = 0; k < K; k++) {
        u64 d = mul2(A.x, PA[k].x);
        d = ffma2(A.y, PA[k].y, d);
        d = ffma2(B.x, PB[k].x, d);
        d = ffma2(B.y, PB[k].y, d);
        v[k] = hadd2(d);
    }
    ssout = hadd2(ss2);
}

// broadcast max (3 shuffles) then ballot-argmax (first-max tiebreak).
// dv per fold8 layout: lane l holds sum for k = l >> 2.
__device__ __forceinline__ int argmax8_ballot(float dv)
{
    float m = dv;
    m = fmaxf(m, __shfl_xor_sync(FULLM, m, 4));
    m = fmaxf(m, __shfl_xor_sync(FULLM, m, 8));
    m = fmaxf(m, __shfl_xor_sync(FULLM, m, 16));
    unsigned mask = __ballot_sync(FULLM, dv == m);
    return (__ffs(mask) - 1) >> 2;
}

// ============================================================================
// Kernel 1: assignment + per-cluster normalized sums (per-block partials)
// ============================================================================
__global__ void __launch_bounds__(TPB, 7)
k_assign(const float* __restrict__ src, const float* __restrict__ protos, int N)
{
    __shared__ float s_acc[WPB * K * D];   // 16 KB: [warp][k][col]
    __shared__ int   s_icnt[WPB * K];

    const int tid  = threadIdx.x;
    const int lane = tid & 31;
    const int warp = tid >> 5;

    {
        float4* z4 = (float4*)s_acc;
#pragma unroll
        for (int i = tid; i < WPB * K * D / 4; i += TPB) z4[i] = make_float4(0,0,0,0);
    }

    const ulonglong2* up = (const ulonglong2*)protos;
    ulonglong2 PA[K], PB[K];
#pragma unroll
    for (int k = 0; k < K; k++) {
        PA[k] = up[k * 64 + lane];
        PB[k] = up[k * 64 + 32 + lane];
    }
    __syncthreads();

    float* s_accw = s_acc + warp * (K * D);
    int cnt = 0;   // rows assigned to cluster (lane & 7)

    const int gw      = blockIdx.x * WPB + warp;
    const int Npair   = N & ~1;
    const int stride2 = TOTW * 2;

    int base = gw * 2;
    ulonglong2 A0, B0, A1, B1;
    if (base < Npair) {
        const ulonglong2* rp = (const ulonglong2*)src + (size_t)base * 64;
        A0 = rp[lane];        B0 = rp[lane + 32];
        A1 = rp[64 + lane];   B1 = rp[64 + lane + 32];
    }

    while (base < Npair) {
        const int nbase = base + stride2;
        ulonglong2 An0 = A0, Bn0 = B0, An1 = A1, Bn1 = B1;
        if (nbase < Npair) {
            const ulonglong2* np = (const ulonglong2*)src + (size_t)nbase * 64;
            An0 = np[lane];        Bn0 = np[lane + 32];
            An1 = np[64 + lane];   Bn1 = np[64 + lane + 32];
        }

        float v0[K], v1[K], ssa, ssb;
        dots8(A0, B0, PA, PB, v0, ssa);
        dots8(A1, B1, PA, PB, v1, ssb);

        float dv0 = fold8(v0, lane);
        float dv1 = fold8(v1, lane);
        float ss0 = warp_sum(ssa);
        float ss1 = warp_sum(ssb);

        const float inv0 = rsqrtf(fmaxf(ss0, 1e-24f));
        const float inv1 = rsqrtf(fmaxf(ss1, 1e-24f));

        const int bk0 = argmax8_ballot(dv0);
        const int bk1 = argmax8_ballot(dv1);

        cnt += (bk0 == (lane & 7)) + (bk1 == (lane & 7));

        {
            const u64 iv = pk2(inv0, inv0);
            ulonglong2* ap = (ulonglong2*)(s_accw + bk0 * D) + lane;
            ulonglong2 c0 = ap[0];
            c0.x = ffma2(A0.x, iv, c0.x);
            c0.y = ffma2(A0.y, iv, c0.y);
            ap[0] = c0;
            ulonglong2 c1 = ap[32];
            c1.x = ffma2(B0.x, iv, c1.x);
            c1.y = ffma2(B0.y, iv, c1.y);
            ap[32] = c1;
        }
        {
            const u64 iv = pk2(inv1, inv1);
            ulonglong2* ap = (ulonglong2*)(s_accw + bk1 * D) + lane;
            ulonglong2 c0 = ap[0];
            c0.x = ffma2(A1.x, iv, c0.x);
            c0.y = ffma2(A1.y, iv, c0.y);
            ap[0] = c0;
            ulonglong2 c1 = ap[32];
            c1.x = ffma2(B1.x, iv, c1.x);
            c1.y = ffma2(B1.y, iv, c1.y);
            ap[32] = c1;
        }

        A0 = An0; B0 = Bn0; A1 = An1; B1 = Bn1;
        base = nbase;
    }

    // odd tail row (only if N is odd)
    if ((N & 1) && gw == 0) {
        const int row = N - 1;
        const ulonglong2* rp = (const ulonglong2*)src + (size_t)row * 64;
        ulonglong2 A = rp[lane], B = rp[lane + 32];
        float v[K], ssp;
        dots8(A, B, PA, PB, v, ssp);
        float dv = fold8(v, lane);
        float ss = warp_sum(ssp);
        const float inv = rsqrtf(fmaxf(ss, 1e-24f));
        const int bk = argmax8_ballot(dv);
        cnt += (bk == (lane & 7));
        const u64 iv = pk2(inv, inv);
        ulonglong2* ap = (ulonglong2*)(s_accw + bk * D) + lane;
        ulonglong2 c0 = ap[0];
        c0.x = ffma2(A.x, iv, c0.x);
        c0.y = ffma2(A.y, iv, c0.y);
        ap[0] = c0;
        ulonglong2 c1 = ap[32];
        c1.x = ffma2(B.x, iv, c1.x);
        c1.y = ffma2(B.y, iv, c1.y);
        ap[32] = c1;
    }

    // counts: lane tracked cluster (lane & 7); fold lanes l^8, l^16
    cnt += __shfl_xor_sync(FULLM, cnt, 8);
    cnt += __shfl_xor_sync(FULLM, cnt, 16);
    if (lane < K) s_icnt[warp * K + lane] = cnt;
    __syncthreads();

    for (int e = tid; e < K * D; e += TPB) {
        g_part_sums[blockIdx.x * (K * D) + e] = s_acc[e] + s_acc[e + K * D];
    }
    if (tid < K) {
        g_part_counts[blockIdx.x * K + tid] = s_icnt[tid] + s_icnt[K + tid];
    }
}

// ============================================================================
// Kernel 2: reduce CTAS partial blocks -> 8 mid blocks (coalesced)
// ============================================================================
#define RCHUNK 130   // ceil(1036 / 8)
__global__ void k_reduce1()
{
    const int be = blockIdx.x & 7;
    const int bb = blockIdx.x >> 3;
    const int e  = be * 256 + threadIdx.x;
    float s = 0.0f;
    const int b0 = bb * RCHUNK;
    const int b1 = min(b0 + RCHUNK, CTAS);
    for (int b = b0; b < b1; b++) s += g_part_sums[b * (K * D) + e];
    g_mid[bb * (K * D) + e] = s;
}

// ============================================================================
// Kernel 3: final reduce + prototype EMA update + renormalize (1 block)
// ============================================================================
__global__ void k_update(const float* __restrict__ protos)
{
    __shared__ float s_sums[K * D];
    __shared__ int   s_cnt[K];

    const int tid  = threadIdx.x;
    const int lane = tid & 31;
    const int warp = tid >> 5;

    for (int e = tid; e < K * D; e += 256) {
        float s = 0.0f;
#pragma unroll
        for (int m = 0; m < 8; m++) s += g_mid[m * (K * D) + e];
        s_sums[e] = s;
    }
    {
        int c = 0;
        for (int b = lane; b < CTAS; b += 32) c += g_part_counts[b * K + warp];
        c = __reduce_add_sync(FULLM, c);
        if (lane == 0) s_cnt[warp] = c;
    }
    __syncthreads();

    const int k = warp;   // 8 warps = 8 clusters
    const float4* s4 = (const float4*)s_sums;
    float4 s1 = s4[k * 64 + lane];
    float4 s2 = s4[k * 64 + 32 + lane];

    const int   c = s_cnt[k];
    const float rr = 1.0f / fmaxf((float)c, 1.0f);
    float4 m1 = make_float4(s1.x*rr, s1.y*rr, s1.z*rr, s1.w*rr);
    float4 m2 = make_float4(s2.x*rr, s2.y*rr, s2.z*rr, s2.w*rr);

    float ss = m1.x*m1.x + m1.y*m1.y + m1.z*m1.z + m1.w*m1.w
             + m2.x*m2.x + m2.y*m2.y + m2.z*m2.z + m2.w*m2.w;
    ss = warp_sum(ss);
    const float inv = 1.0f / fmaxf(sqrtf(ss), 1e-12f);

    const float4* p4 = (const float4*)protos;
    const float4 p1 = p4[k * 64 + lane];
    const float4 p2 = p4[k * 64 + 32 + lane];

    float4 u1, u2;
    if (c > 0) {
        u1 = make_float4(0.9f*p1.x + 0.1f*m1.x*inv, 0.9f*p1.y + 0.1f*m1.y*inv,
                         0.9f*p1.z + 0.1f*m1.z*inv, 0.9f*p1.w + 0.1f*m1.w*inv);
        u2 = make_float4(0.9f*p2.x + 0.1f*m2.x*inv, 0.9f*p2.y + 0.1f*m2.y*inv,
                         0.9f*p2.z + 0.1f*m2.z*inv, 0.9f*p2.w + 0.1f*m2.w*inv);
    } else {
        u1 = p1; u2 = p2;
    }

    float ss2 = u1.x*u1.x + u1.y*u1.y + u1.z*u1.z + u1.w*u1.w
              + u2.x*u2.x + u2.y*u2.y + u2.z*u2.z + u2.w*u2.w;
    ss2 = warp_sum(ss2);
    const float inv2 = 1.0f / fmaxf(sqrtf(ss2), 1e-12f);

    float4* o4 = (float4*)g_protos_new;
    o4[k * 64 + lane]      = make_float4(u1.x*inv2, u1.y*inv2, u1.z*inv2, u1.w*inv2);
    o4[k * 64 + 32 + lane] = make_float4(u2.x*inv2, u2.y*inv2, u2.z*inv2, u2.w*inv2);
}

// ============================================================================
// Kernel 4: target loss partials — accumulates sum of max cos-sim
// ============================================================================
__global__ void __launch_bounds__(TPB, 7)
k_loss(const float* __restrict__ tgt, int N)
{
    __shared__ float s_l[WPB];

    const int tid  = threadIdx.x;
    const int lane = tid & 31;
    const int warp = tid >> 5;

    const ulonglong2* up = (const ulonglong2*)g_protos_new;
    ulonglong2 PA[K], PB[K];
#pragma unroll
    for (int k = 0; k < K; k++) {
        PA[k] = up[k * 64 + lane];
        PB[k] = up[k * 64 + 32 + lane];
    }

    const int gw      = blockIdx.x * WPB + warp;
    const int Npair   = N & ~1;
    const int stride2 = TOTW * 2;

    float lsum = 0.0f;

    int base = gw * 2;
    ulonglong2 A0, B0, A1, B1;
    if (base < Npair) {
        const ulonglong2* rp = (const ulonglong2*)tgt + (size_t)base * 64;
        A0 = rp[lane];        B0 = rp[lane + 32];
        A1 = rp[64 + lane];   B1 = rp[64 + lane + 32];
    }

    while (base < Npair) {
        const int nbase = base + stride2;
        ulonglong2 An0 = A0, Bn0 = B0, An1 = A1, Bn1 = B1;
        if (nbase < Npair) {
            const ulonglong2* np = (const ulonglong2*)tgt + (size_t)nbase * 64;
            An0 = np[lane];        Bn0 = np[lane + 32];
            An1 = np[64 + lane];   Bn1 = np[64 + lane + 32];
        }

        float v0[K], v1[K], ssa, ssb;
        dots8(A0, B0, PA, PB, v0, ssa);
        dots8(A1, B1, PA, PB, v1, ssb);

        float dv0 = fold8(v0, lane);
        float dv1 = fold8(v1, lane);
        float ss0 = warp_sum(ssa);
        float ss1 = warp_sum(ssb);

        dv0 = fmaxf(dv0, __shfl_xor_sync(FULLM, dv0, 4));
        dv1 = fmaxf(dv1, __shfl_xor_sync(FULLM, dv1, 4));
        dv0 = fmaxf(dv0, __shfl_xor_sync(FULLM, dv0, 8));
        dv1 = fmaxf(dv1, __shfl_xor_sync(FULLM, dv1, 8));
        dv0 = fmaxf(dv0, __shfl_xor_sync(FULLM, dv0, 16));
        dv1 = fmaxf(dv1, __shfl_xor_sync(FULLM, dv1, 16));

        if (lane == 0) {
            lsum += dv0 * rsqrtf(fmaxf(ss0, 1e-24f));
            lsum += dv1 * rsqrtf(fmaxf(ss1, 1e-24f));
        }

        A0 = An0; B0 = Bn0; A1 = An1; B1 = Bn1;
        base = nbase;
    }

    if ((N & 1) && gw == 0) {
        const int row = N - 1;
        const ulonglong2* rp = (const ulonglong2*)tgt + (size_t)row * 64;
        ulonglong2 A = rp[lane], B = rp[lane + 32];
        float v[K], ssp;
        dots8(A, B, PA, PB, v, ssp);
        float dv = fold8(v, lane);
        float ss = warp_sum(ssp);
        dv = fmaxf(dv, __shfl_xor_sync(FULLM, dv, 4));
        dv = fmaxf(dv, __shfl_xor_sync(FULLM, dv, 8));
        dv = fmaxf(dv, __shfl_xor_sync(FULLM, dv, 16));
        if (lane == 0) lsum += dv * rsqrtf(fmaxf(ss, 1e-24f));
    }

    if (lane == 0) s_l[warp] = lsum;
    __syncthreads();
    if (tid == 0) {
        g_part_loss[blockIdx.x] = s_l[0] + s_l[1];
    }
}

// ============================================================================
// Kernel 5: final mean:  out = 1 - (sum of max cos) / Nt
// ============================================================================
__global__ void k_final(float* __restrict__ out, int Nt)
{
    __shared__ float sw[16];
    const int tid  = threadIdx.x;
    const int lane = tid & 31;
    const int warp = tid >> 5;

    float v = 0.0f;
    for (int i = tid; i < CTAS; i += 512) v += g_part_loss[i];
    v = warp_sum(v);
    if (lane == 0) sw[warp] = v;
    __syncthreads();
    if (tid == 0) {
        float s = 0.0f;
#pragma unroll
        for (int w = 0; w < 16; w++) s += sw[w];
        out[0] = 1.0f - s / (float)Nt;
    }
}

// ============================================================================
extern "C" void kernel_launch(void* const* d_in, const int* in_sizes, int n_in,
                              void* d_out, int out_size)
{
    const float* src    = (const float*)d_in[0];
    const float* tgt    = (const float*)d_in[1];
    const float* protos = (const float*)d_in[2];
    float* out = (float*)d_out;

    const int Ns = in_sizes[0] / D;
    const int Nt = in_sizes[1] / D;

    k_assign<<<CTAS, TPB>>>(src, protos, Ns);
    k_reduce1<<<64, 256>>>();
    k_update<<<1, 256>>>(protos);
    k_loss<<<CTAS, TPB>>>(tgt, Nt);
    k_final<<<1, 512>>>(out, Nt);
}

// round 8
// speedup vs baseline: 1.4183x; 1.0308x over previous
#include <cuda_runtime.h>
#include <math.h>
#include <stdint.h>

#define D       256
#define K       8
#define FULLM   0xffffffffu

// both big kernels: 64 threads (2 warps), 6 CTAs/SM
#define TPB     64
#define WPB     2
#define CTAS    888          // 6 * 148
#define TOTW    (CTAS * WPB) // 1776 warps

typedef unsigned long long u64;

struct Pair { ulonglong2 a, b, c, d; };   // two consecutive rows (a,b)=row0 (c,d)=row1

// ---- device scratch (no allocations allowed) ----
__device__ float g_part_sums[CTAS * K * D];   // per-block per-cluster sums
__device__ int   g_part_counts[CTAS * K];
__device__ float g_mid[8 * K * D];            // stage-2 partials
__device__ float g_part_loss[CTAS];
__device__ float g_protos_new[K * D];

// ---------------- f32x2 packed helpers ----------------
__device__ __forceinline__ u64 pk2(float lo, float hi) {
    u64 r; asm("mov.b64 %0, {%1, %2};" : "=l"(r) : "f"(lo), "f"(hi)); return r;
}
__device__ __forceinline__ float hadd2(u64 v) {
    float lo, hi; asm("mov.b64 {%0, %1}, %2;" : "=f"(lo), "=f"(hi) : "l"(v));
    return lo + hi;
}
__device__ __forceinline__ u64 mul2(u64 a, u64 b) {
    u64 d; asm("mul.rn.f32x2 %0, %1, %2;" : "=l"(d) : "l"(a), "l"(b)); return d;
}
__device__ __forceinline__ u64 ffma2(u64 a, u64 b, u64 c) {
    u64 d; asm("fma.rn.f32x2 %0, %1, %2, %3;" : "=l"(d) : "l"(a), "l"(b), "l"(c)); return d;
}

__device__ __forceinline__ float warp_sum(float v) {
    v += __shfl_xor_sync(FULLM, v, 16);
    v += __shfl_xor_sync(FULLM, v, 8);
    v += __shfl_xor_sync(FULLM, v, 4);
    v += __shfl_xor_sync(FULLM, v, 2);
    v += __shfl_xor_sync(FULLM, v, 1);
    return v;
}

// Folded 8-value warp reduction: 9 shuffles. On return, lane l holds the
// full 32-lane sum of value index k(l) = (l >> 2) & 7.
__device__ __forceinline__ float fold8(const float* v, int lane) {
    float v0, v1, v2, v3;
    {
        bool hi = (lane & 16) != 0;
        float k0 = hi ? v[4] : v[0], k1 = hi ? v[5] : v[1];
        float k2 = hi ? v[6] : v[2], k3 = hi ? v[7] : v[3];
        float s0 = hi ? v[0] : v[4], s1 = hi ? v[1] : v[5];
        float s2 = hi ? v[2] : v[6], s3 = hi ? v[3] : v[7];
        v0 = k0 + __shfl_xor_sync(FULLM, s0, 16);
        v1 = k1 + __shfl_xor_sync(FULLM, s1, 16);
        v2 = k2 + __shfl_xor_sync(FULLM, s2, 16);
        v3 = k3 + __shfl_xor_sync(FULLM, s3, 16);
    }
    {
        bool hi = (lane & 8) != 0;
        float k0 = hi ? v2 : v0, k1 = hi ? v3 : v1;
        float s0 = hi ? v0 : v2, s1 = hi ? v1 : v3;
        v0 = k0 + __shfl_xor_sync(FULLM, s0, 8);
        v1 = k1 + __shfl_xor_sync(FULLM, s1, 8);
    }
    {
        bool hi = (lane & 4) != 0;
        float k0 = hi ? v1 : v0;
        float s0 = hi ? v0 : v1;
        v0 = k0 + __shfl_xor_sync(FULLM, s0, 4);
    }
    v0 += __shfl_xor_sync(FULLM, v0, 2);
    v0 += __shfl_xor_sync(FULLM, v0, 1);
    return v0;
}

// per-row core: packed dots vs 8 prototypes + self norm (no reductions)
__device__ __forceinline__ void dots8(const ulonglong2& A, const ulonglong2& B,
                                      const ulonglong2* PA, const ulonglong2* PB,
                                      float* v, float& ssout)
{
    u64 ss2 = mul2(A.x, A.x);
    ss2 = ffma2(A.y, A.y, ss2);
    ss2 = ffma2(B.x, B.x, ss2);
    ss2 = ffma2(B.y, B.y, ss2);
#pragma unroll
    for (int k = 0; k < K; k++) {
        u64 d = mul2(A.x, PA[k].x);
        d = ffma2(A.y, PA[k].y, d);
        d = ffma2(B.x, PB[k].x, d);
        d = ffma2(B.y, PB[k].y, d);
        v[k] = hadd2(d);
    }
    ssout = hadd2(ss2);
}

// broadcast max (3 shuffles) then ballot-argmax (first-max tiebreak).
// dv per fold8 layout: lane l holds sum for k = l >> 2.
__device__ __forceinline__ int argmax8_ballot(float dv)
{
    float m = dv;
    m = fmaxf(m, __shfl_xor_sync(FULLM, m, 4));
    m = fmaxf(m, __shfl_xor_sync(FULLM, m, 8));
    m = fmaxf(m, __shfl_xor_sync(FULLM, m, 16));
    unsigned mask = __ballot_sync(FULLM, dv == m);
    return (__ffs(mask) - 1) >> 2;
}

// ============================================================================
// Kernel 1: assignment + per-cluster normalized sums (per-block partials)
// Depth-2 software pipeline: 3 rotating pair buffers, unroll-by-3.
// ============================================================================
__global__ void __launch_bounds__(TPB, 6)
k_assign(const float* __restrict__ src, const float* __restrict__ protos, int N)
{
    __shared__ float s_acc[WPB * K * D];   // 16 KB: [warp][k][col]
    __shared__ int   s_icnt[WPB * K];

    const int tid  = threadIdx.x;
    const int lane = tid & 31;
    const int warp = tid >> 5;

    {
        float4* z4 = (float4*)s_acc;
#pragma unroll
        for (int i = tid; i < WPB * K * D / 4; i += TPB) z4[i] = make_float4(0,0,0,0);
    }

    const ulonglong2* up = (const ulonglong2*)protos;
    ulonglong2 PA[K], PB[K];
#pragma unroll
    for (int k = 0; k < K; k++) {
        PA[k] = up[k * 64 + lane];
        PB[k] = up[k * 64 + 32 + lane];
    }
    __syncthreads();

    float* s_accw = s_acc + warp * (K * D);
    int cnt = 0;   // rows assigned to cluster (lane & 7)

    const int gw    = blockIdx.x * WPB + warp;
    const int Npair = N >> 1;

    auto loadP = [&](int i, Pair& P) {
        int p = gw + i * TOTW;
        if (p >= Npair) p = Npair - 1;
        const ulonglong2* rp = (const ulonglong2*)src + (size_t)p * 128;
        P.a = rp[lane];      P.b = rp[lane + 32];
        P.c = rp[64 + lane]; P.d = rp[96 + lane];
    };

    auto stepP = [&](const Pair& P, int i) {
        float v0[K], v1[K], ssa, ssb;
        dots8(P.a, P.b, PA, PB, v0, ssa);
        dots8(P.c, P.d, PA, PB, v1, ssb);

        float dv0 = fold8(v0, lane);
        float dv1 = fold8(v1, lane);
        float ss0 = warp_sum(ssa);
        float ss1 = warp_sum(ssb);

        const float inv0 = rsqrtf(fmaxf(ss0, 1e-24f));
        const float inv1 = rsqrtf(fmaxf(ss1, 1e-24f));

        const int bk0 = argmax8_ballot(dv0);
        const int bk1 = argmax8_ballot(dv1);

        if (gw + i * TOTW < Npair) {
            cnt += (bk0 == (lane & 7)) + (bk1 == (lane & 7));
            {
                const u64 iv = pk2(inv0, inv0);
                ulonglong2* ap = (ulonglong2*)(s_accw + bk0 * D) + lane;
                ulonglong2 c0 = ap[0];
                c0.x = ffma2(P.a.x, iv, c0.x);
                c0.y = ffma2(P.a.y, iv, c0.y);
                ap[0] = c0;
                ulonglong2 c1 = ap[32];
                c1.x = ffma2(P.b.x, iv, c1.x);
                c1.y = ffma2(P.b.y, iv, c1.y);
                ap[32] = c1;
            }
            {
                const u64 iv = pk2(inv1, inv1);
                ulonglong2* ap = (ulonglong2*)(s_accw + bk1 * D) + lane;
                ulonglong2 c0 = ap[0];
                c0.x = ffma2(P.c.x, iv, c0.x);
                c0.y = ffma2(P.c.y, iv, c0.y);
                ap[0] = c0;
                ulonglong2 c1 = ap[32];
                c1.x = ffma2(P.d.x, iv, c1.x);
                c1.y = ffma2(P.d.y, iv, c1.y);
                ap[32] = c1;
            }
        }
    };

    Pair b0, b1, b2;
    loadP(0, b0);
    loadP(1, b1);
    const int iters = (Npair - gw + TOTW - 1) / TOTW;
    for (int i = 0; i < iters; i += 3) {
        loadP(i + 2, b2); stepP(b0, i);
        loadP(i + 3, b0); stepP(b1, i + 1);
        loadP(i + 4, b1); stepP(b2, i + 2);
    }

    // odd tail row (only if N is odd)
    if ((N & 1) && gw == 0) {
        const int row = N - 1;
        const ulonglong2* rp = (const ulonglong2*)src + (size_t)row * 64;
        ulonglong2 A = rp[lane], B = rp[lane + 32];
        float v[K], ssp;
        dots8(A, B, PA, PB, v, ssp);
        float dv = fold8(v, lane);
        float ss = warp_sum(ssp);
        const float inv = rsqrtf(fmaxf(ss, 1e-24f));
        const int bk = argmax8_ballot(dv);
        cnt += (bk == (lane & 7));
        const u64 iv = pk2(inv, inv);
        ulonglong2* ap = (ulonglong2*)(s_accw + bk * D) + lane;
        ulonglong2 c0 = ap[0];
        c0.x = ffma2(A.x, iv, c0.x);
        c0.y = ffma2(A.y, iv, c0.y);
        ap[0] = c0;
        ulonglong2 c1 = ap[32];
        c1.x = ffma2(B.x, iv, c1.x);
        c1.y = ffma2(B.y, iv, c1.y);
        ap[32] = c1;
    }

    // counts: lane tracked cluster (lane & 7); fold lanes l^8, l^16
    cnt += __shfl_xor_sync(FULLM, cnt, 8);
    cnt += __shfl_xor_sync(FULLM, cnt, 16);
    if (lane < K) s_icnt[warp * K + lane] = cnt;
    __syncthreads();

    for (int e = tid; e < K * D; e += TPB) {
        g_part_sums[blockIdx.x * (K * D) + e] = s_acc[e] + s_acc[e + K * D];
    }
    if (tid < K) {
        g_part_counts[blockIdx.x * K + tid] = s_icnt[tid] + s_icnt[K + tid];
    }
}

// ============================================================================
// Kernel 2: reduce CTAS partial blocks -> 8 mid blocks (coalesced)
// ============================================================================
#define RCHUNK 111   // ceil(888 / 8)
__global__ void k_reduce1()
{
    const int be = blockIdx.x & 7;
    const int bb = blockIdx.x >> 3;
    const int e  = be * 256 + threadIdx.x;
    float s = 0.0f;
    const int b0 = bb * RCHUNK;
    const int b1 = min(b0 + RCHUNK, CTAS);
    for (int b = b0; b < b1; b++) s += g_part_sums[b * (K * D) + e];
    g_mid[bb * (K * D) + e] = s;
}

// ============================================================================
// Kernel 3: final reduce + prototype EMA update + renormalize (1 block)
// ============================================================================
__global__ void k_update(const float* __restrict__ protos)
{
    __shared__ float s_sums[K * D];
    __shared__ int   s_cnt[K];

    const int tid  = threadIdx.x;
    const int lane = tid & 31;
    const int warp = tid >> 5;

    for (int e = tid; e < K * D; e += 256) {
        float s = 0.0f;
#pragma unroll
        for (int m = 0; m < 8; m++) s += g_mid[m * (K * D) + e];
        s_sums[e] = s;
    }
    {
        int c = 0;
        for (int b = lane; b < CTAS; b += 32) c += g_part_counts[b * K + warp];
        c = __reduce_add_sync(FULLM, c);
        if (lane == 0) s_cnt[warp] = c;
    }
    __syncthreads();

    const int k = warp;   // 8 warps = 8 clusters
    const float4* s4 = (const float4*)s_sums;
    float4 s1 = s4[k * 64 + lane];
    float4 s2 = s4[k * 64 + 32 + lane];

    const int   c = s_cnt[k];
    const float rr = 1.0f / fmaxf((float)c, 1.0f);
    float4 m1 = make_float4(s1.x*rr, s1.y*rr, s1.z*rr, s1.w*rr);
    float4 m2 = make_float4(s2.x*rr, s2.y*rr, s2.z*rr, s2.w*rr);

    float ss = m1.x*m1.x + m1.y*m1.y + m1.z*m1.z + m1.w*m1.w
             + m2.x*m2.x + m2.y*m2.y + m2.z*m2.z + m2.w*m2.w;
    ss = warp_sum(ss);
    const float inv = 1.0f / fmaxf(sqrtf(ss), 1e-12f);

    const float4* p4 = (const float4*)protos;
    const float4 p1 = p4[k * 64 + lane];
    const float4 p2 = p4[k * 64 + 32 + lane];

    float4 u1, u2;
    if (c > 0) {
        u1 = make_float4(0.9f*p1.x + 0.1f*m1.x*inv, 0.9f*p1.y + 0.1f*m1.y*inv,
                         0.9f*p1.z + 0.1f*m1.z*inv, 0.9f*p1.w + 0.1f*m1.w*inv);
        u2 = make_float4(0.9f*p2.x + 0.1f*m2.x*inv, 0.9f*p2.y + 0.1f*m2.y*inv,
                         0.9f*p2.z + 0.1f*m2.z*inv, 0.9f*p2.w + 0.1f*m2.w*inv);
    } else {
        u1 = p1; u2 = p2;
    }

    float ss2 = u1.x*u1.x + u1.y*u1.y + u1.z*u1.z + u1.w*u1.w
              + u2.x*u2.x + u2.y*u2.y + u2.z*u2.z + u2.w*u2.w;
    ss2 = warp_sum(ss2);
    const float inv2 = 1.0f / fmaxf(sqrtf(ss2), 1e-12f);

    float4* o4 = (float4*)g_protos_new;
    o4[k * 64 + lane]      = make_float4(u1.x*inv2, u1.y*inv2, u1.z*inv2, u1.w*inv2);
    o4[k * 64 + 32 + lane] = make_float4(u2.x*inv2, u2.y*inv2, u2.z*inv2, u2.w*inv2);
}

// ============================================================================
// Kernel 4: target loss partials — accumulates sum of max cos-sim
// Depth-2 software pipeline: 3 rotating pair buffers, unroll-by-3.
// ============================================================================
__global__ void __launch_bounds__(TPB, 6)
k_loss(const float* __restrict__ tgt, int N)
{
    __shared__ float s_l[WPB];

    const int tid  = threadIdx.x;
    const int lane = tid & 31;
    const int warp = tid >> 5;

    const ulonglong2* up = (const ulonglong2*)g_protos_new;
    ulonglong2 PA[K], PB[K];
#pragma unroll
    for (int k = 0; k < K; k++) {
        PA[k] = up[k * 64 + lane];
        PB[k] = up[k * 64 + 32 + lane];
    }

    const int gw    = blockIdx.x * WPB + warp;
    const int Npair = N >> 1;

    float lsum = 0.0f;

    auto loadP = [&](int i, Pair& P) {
        int p = gw + i * TOTW;
        if (p >= Npair) p = Npair - 1;
        const ulonglong2* rp = (const ulonglong2*)tgt + (size_t)p * 128;
        P.a = rp[lane];      P.b = rp[lane + 32];
        P.c = rp[64 + lane]; P.d = rp[96 + lane];
    };

    auto stepL = [&](const Pair& P, int i) {
        float v0[K], v1[K], ssa, ssb;
        dots8(P.a, P.b, PA, PB, v0, ssa);
        dots8(P.c, P.d, PA, PB, v1, ssb);

        float dv0 = fold8(v0, lane);
        float dv1 = fold8(v1, lane);
        float ss0 = warp_sum(ssa);
        float ss1 = warp_sum(ssb);

        dv0 = fmaxf(dv0, __shfl_xor_sync(FULLM, dv0, 4));
        dv1 = fmaxf(dv1, __shfl_xor_sync(FULLM, dv1, 4));
        dv0 = fmaxf(dv0, __shfl_xor_sync(FULLM, dv0, 8));
        dv1 = fmaxf(dv1, __shfl_xor_sync(FULLM, dv1, 8));
        dv0 = fmaxf(dv0, __shfl_xor_sync(FULLM, dv0, 16));
        dv1 = fmaxf(dv1, __shfl_xor_sync(FULLM, dv1, 16));

        if (lane == 0 && (gw + i * TOTW) < Npair) {
            lsum += dv0 * rsqrtf(fmaxf(ss0, 1e-24f));
            lsum += dv1 * rsqrtf(fmaxf(ss1, 1e-24f));
        }
    };

    Pair b0, b1, b2;
    loadP(0, b0);
    loadP(1, b1);
    const int iters = (Npair - gw + TOTW - 1) / TOTW;
    for (int i = 0; i < iters; i += 3) {
        loadP(i + 2, b2); stepL(b0, i);
        loadP(i + 3, b0); stepL(b1, i + 1);
        loadP(i + 4, b1); stepL(b2, i + 2);
    }

    if ((N & 1) && gw == 0) {
        const int row = N - 1;
        const ulonglong2* rp = (const ulonglong2*)tgt + (size_t)row * 64;
        ulonglong2 A = rp[lane], B = rp[lane + 32];
        float v[K], ssp;
        dots8(A, B, PA, PB, v, ssp);
        float dv = fold8(v, lane);
        float ss = warp_sum(ssp);
        dv = fmaxf(dv, __shfl_xor_sync(FULLM, dv, 4));
        dv = fmaxf(dv, __shfl_xor_sync(FULLM, dv, 8));
        dv = fmaxf(dv, __shfl_xor_sync(FULLM, dv, 16));
        if (lane == 0) lsum += dv * rsqrtf(fmaxf(ss, 1e-24f));
    }

    if (lane == 0) s_l[warp] = lsum;
    __syncthreads();
    if (tid == 0) {
        g_part_loss[blockIdx.x] = s_l[0] + s_l[1];
    }
}

// ============================================================================
// Kernel 5: final mean:  out = 1 - (sum of max cos) / Nt
// ============================================================================
__global__ void k_final(float* __restrict__ out, int Nt)
{
    __shared__ float sw[16];
    const int tid  = threadIdx.x;
    const int lane = tid & 31;
    const int warp = tid >> 5;

    float v = 0.0f;
    for (int i = tid; i < CTAS; i += 512) v += g_part_loss[i];
    v = warp_sum(v);
    if (lane == 0) sw[warp] = v;
    __syncthreads();
    if (tid == 0) {
        float s = 0.0f;
#pragma unroll
        for (int w = 0; w < 16; w++) s += sw[w];
        out[0] = 1.0f - s / (float)Nt;
    }
}

// ============================================================================
extern "C" void kernel_launch(void* const* d_in, const int* in_sizes, int n_in,
                              void* d_out, int out_size)
{
    const float* src    = (const float*)d_in[0];
    const float* tgt    = (const float*)d_in[1];
    const float* protos = (const float*)d_in[2];
    float* out = (float*)d_out;

    const int Ns = in_sizes[0] / D;
    const int Nt = in_sizes[1] / D;

    k_assign<<<CTAS, TPB>>>(src, protos, Ns);
    k_reduce1<<<64, 256>>>();
    k_update<<<1, 256>>>(protos);
    k_loss<<<CTAS, TPB>>>(tgt, Nt);
    k_final<<<1, 512>>>(out, Nt);
}

// round 9
// speedup vs baseline: 1.4962x; 1.0549x over previous
#include <cuda_runtime.h>
#include <math.h>
#include <stdint.h>

#define D       256
#define K       8
#define FULLM   0xffffffffu

// ---- k_assign config (R5, proven) ----
#define A_TPB   128
#define A_WPB   4
#define A_GRID  444          // 3 * 148
#define NWARPS  (A_GRID * A_WPB)

// ---- k_loss (MMA) config ----
#define L_TPB   64
#define L_CTAS  740          // 5 * 148
#define L_TOTW  (L_CTAS * 2)
#define PITCH   260          // floats; 260 mod 32 = 4 -> conflict-free frag LDS

typedef unsigned long long u64;

// ---- device scratch (no allocations allowed) ----
__device__ float g_part_sums[A_GRID * K * D];
__device__ int   g_part_counts[A_GRID * K];
__device__ float g_mid[8 * K * D];
__device__ float g_part_loss[L_CTAS];
__device__ float g_protos_new[K * D];

// ---------------- f32x2 packed helpers ----------------
__device__ __forceinline__ u64 pk2(float lo, float hi) {
    u64 r; asm("mov.b64 %0, {%1, %2};" : "=l"(r) : "f"(lo), "f"(hi)); return r;
}
__device__ __forceinline__ float hadd2(u64 v) {
    float lo, hi; asm("mov.b64 {%0, %1}, %2;" : "=f"(lo), "=f"(hi) : "l"(v));
    return lo + hi;
}
__device__ __forceinline__ u64 mul2(u64 a, u64 b) {
    u64 d; asm("mul.rn.f32x2 %0, %1, %2;" : "=l"(d) : "l"(a), "l"(b)); return d;
}
__device__ __forceinline__ u64 ffma2(u64 a, u64 b, u64 c) {
    u64 d; asm("fma.rn.f32x2 %0, %1, %2, %3;" : "=l"(d) : "l"(a), "l"(b), "l"(c)); return d;
}
__device__ __forceinline__ void cp16(uint32_t s, const void* g) {
    asm volatile("cp.async.cg.shared.global [%0], [%1], 16;" :: "r"(s), "l"(g));
}

__device__ __forceinline__ float warp_sum(float v) {
    v += __shfl_xor_sync(FULLM, v, 16);
    v += __shfl_xor_sync(FULLM, v, 8);
    v += __shfl_xor_sync(FULLM, v, 4);
    v += __shfl_xor_sync(FULLM, v, 2);
    v += __shfl_xor_sync(FULLM, v, 1);
    return v;
}

// Folded 8-value warp reduction (R5): lane l holds full sum of k = (l>>2)&7.
__device__ __forceinline__ float fold8(const float* v, int lane) {
    float v0, v1, v2, v3;
    {
        bool hi = (lane & 16) != 0;
        float k0 = hi ? v[4] : v[0], k1 = hi ? v[5] : v[1];
        float k2 = hi ? v[6] : v[2], k3 = hi ? v[7] : v[3];
        float s0 = hi ? v[0] : v[4], s1 = hi ? v[1] : v[5];
        float s2 = hi ? v[2] : v[6], s3 = hi ? v[3] : v[7];
        v0 = k0 + __shfl_xor_sync(FULLM, s0, 16);
        v1 = k1 + __shfl_xor_sync(FULLM, s1, 16);
        v2 = k2 + __shfl_xor_sync(FULLM, s2, 16);
        v3 = k3 + __shfl_xor_sync(FULLM, s3, 16);
    }
    {
        bool hi = (lane & 8) != 0;
        float k0 = hi ? v2 : v0, k1 = hi ? v3 : v1;
        float s0 = hi ? v0 : v2, s1 = hi ? v1 : v3;
        v0 = k0 + __shfl_xor_sync(FULLM, s0, 8);
        v1 = k1 + __shfl_xor_sync(FULLM, s1, 8);
    }
    {
        bool hi = (lane & 4) != 0;
        float k0 = hi ? v1 : v0;
        float s0 = hi ? v0 : v1;
        v0 = k0 + __shfl_xor_sync(FULLM, s0, 4);
    }
    v0 += __shfl_xor_sync(FULLM, v0, 2);
    v0 += __shfl_xor_sync(FULLM, v0, 1);
    return v0;
}

__device__ __forceinline__ void dots8(const ulonglong2& A, const ulonglong2& B,
                                      const ulonglong2* PA, const ulonglong2* PB,
                                      float* v, float& ssout)
{
    u64 ss2 = mul2(A.x, A.x);
    ss2 = ffma2(A.y, A.y, ss2);
    ss2 = ffma2(B.x, B.x, ss2);
    ss2 = ffma2(B.y, B.y, ss2);
#pragma unroll
    for (int k = 0; k < K; k++) {
        u64 d = mul2(A.x, PA[k].x);
        d = ffma2(A.y, PA[k].y, d);
        d = ffma2(B.x, PB[k].x, d);
        d = ffma2(B.y, PB[k].y, d);
        v[k] = hadd2(d);
    }
    ssout = hadd2(ss2);
}

__device__ __forceinline__ int argmax8(float dv, int lane)
{
    float bv = dv;
    int   bk = (lane >> 2) & 7;
#pragma unroll
    for (int s = 4; s <= 16; s <<= 1) {
        float ov = __shfl_xor_sync(FULLM, bv, s);
        int   ok = __shfl_xor_sync(FULLM, bk, s);
        if (ov > bv || (ov == bv && ok < bk)) { bv = ov; bk = ok; }
    }
    return bk;
}

// ============================================================================
// Kernel 1 (R5 verbatim): assignment + per-cluster normalized sums
// ============================================================================
__global__ void __launch_bounds__(A_TPB, 3)
k_assign(const float* __restrict__ src, const float* __restrict__ protos, int N)
{
    __shared__ float s_acc[A_WPB * K * D];   // 32 KB: [warp][k][col]
    __shared__ int   s_icnt[A_WPB * K];

    const int tid  = threadIdx.x;
    const int lane = tid & 31;
    const int warp = tid >> 5;

    for (int e = tid; e < A_WPB * K * D; e += A_TPB) s_acc[e] = 0.0f;

    const ulonglong2* up = (const ulonglong2*)protos;
    ulonglong2 PA[K], PB[K];
#pragma unroll
    for (int k = 0; k < K; k++) {
        PA[k] = up[k * 64 + lane];
        PB[k] = up[k * 64 + 32 + lane];
    }
    __syncthreads();

    int cnt = 0;

    const int gw      = blockIdx.x * A_WPB + warp;
    const int Npair   = N & ~1;
    const int stride2 = NWARPS * 2;

    int base = gw * 2;
    ulonglong2 A0, B0, A1, B1;
    if (base < Npair) {
        const ulonglong2* rp = (const ulonglong2*)src + (size_t)base * 64;
        A0 = rp[lane];        B0 = rp[lane + 32];
        A1 = rp[64 + lane];   B1 = rp[64 + lane + 32];
    }

    while (base < Npair) {
        const int nbase = base + stride2;
        ulonglong2 An0 = A0, Bn0 = B0, An1 = A1, Bn1 = B1;
        if (nbase < Npair) {
            const ulonglong2* np = (const ulonglong2*)src + (size_t)nbase * 64;
            An0 = np[lane];        Bn0 = np[lane + 32];
            An1 = np[64 + lane];   Bn1 = np[64 + lane + 32];
        }

        float v0[K], v1[K], ssa, ssb;
        dots8(A0, B0, PA, PB, v0, ssa);
        dots8(A1, B1, PA, PB, v1, ssb);

        float dv0 = fold8(v0, lane);
        float dv1 = fold8(v1, lane);
        float ss0 = warp_sum(ssa);
        float ss1 = warp_sum(ssb);

        const float inv0 = rsqrtf(fmaxf(ss0, 1e-24f));
        const float inv1 = rsqrtf(fmaxf(ss1, 1e-24f));

        const int bk0 = argmax8(dv0, lane);
        const int bk1 = argmax8(dv1, lane);

        cnt += (bk0 == (lane & 7)) + (bk1 == (lane & 7));

        {
            const u64 iv = pk2(inv0, inv0);
            ulonglong2* ap = (ulonglong2*)(s_acc + (warp * K + bk0) * D) + lane;
            ulonglong2 c0 = ap[0];
            c0.x = ffma2(A0.x, iv, c0.x);
            c0.y = ffma2(A0.y, iv, c0.y);
            ap[0] = c0;
            ulonglong2 c1 = ap[32];
            c1.x = ffma2(B0.x, iv, c1.x);
            c1.y = ffma2(B0.y, iv, c1.y);
            ap[32] = c1;
        }
        {
            const u64 iv = pk2(inv1, inv1);
            ulonglong2* ap = (ulonglong2*)(s_acc + (warp * K + bk1) * D) + lane;
            ulonglong2 c0 = ap[0];
            c0.x = ffma2(A1.x, iv, c0.x);
            c0.y = ffma2(A1.y, iv, c0.y);
            ap[0] = c0;
            ulonglong2 c1 = ap[32];
            c1.x = ffma2(B1.x, iv, c1.x);
            c1.y = ffma2(B1.y, iv, c1.y);
            ap[32] = c1;
        }

        A0 = An0; B0 = Bn0; A1 = An1; B1 = Bn1;
        base = nbase;
    }

    if ((N & 1) && gw == 0) {
        const int row = N - 1;
        const ulonglong2* rp = (const ulonglong2*)src + (size_t)row * 64;
        ulonglong2 A = rp[lane], B = rp[lane + 32];
        float v[K], ssp;
        dots8(A, B, PA, PB, v, ssp);
        float dv = fold8(v, lane);
        float ss = warp_sum(ssp);
        const float inv = rsqrtf(fmaxf(ss, 1e-24f));
        const int bk = argmax8(dv, lane);
        cnt += (bk == (lane & 7));
        const u64 iv = pk2(inv, inv);
        ulonglong2* ap = (ulonglong2*)(s_acc + (warp * K + bk) * D) + lane;
        ulonglong2 c0 = ap[0];
        c0.x = ffma2(A.x, iv, c0.x);
        c0.y = ffma2(A.y, iv, c0.y);
        ap[0] = c0;
        ulonglong2 c1 = ap[32];
        c1.x = ffma2(B.x, iv, c1.x);
        c1.y = ffma2(B.y, iv, c1.y);
        ap[32] = c1;
    }

    cnt += __shfl_xor_sync(FULLM, cnt, 8);
    cnt += __shfl_xor_sync(FULLM, cnt, 16);
    if (lane < K) s_icnt[warp * K + lane] = cnt;
    __syncthreads();

    for (int e = tid; e < K * D; e += A_TPB) {
        float s = s_acc[e] + s_acc[e + K * D] + s_acc[e + 2 * K * D] + s_acc[e + 3 * K * D];
        g_part_sums[blockIdx.x * (K * D) + e] = s;
    }
    if (tid < K) {
        int c = 0;
#pragma unroll
        for (int w = 0; w < A_WPB; w++) c += s_icnt[w * K + tid];
        g_part_counts[blockIdx.x * K + tid] = c;
    }
}

// ============================================================================
// Kernel 2: reduce A_GRID partial blocks -> 8 mid blocks
// ============================================================================
#define RCHUNK 56   // ceil(444 / 8)
__global__ void k_reduce1()
{
    const int be = blockIdx.x & 7;
    const int bb = blockIdx.x >> 3;
    const int e  = be * 256 + threadIdx.x;
    float s = 0.0f;
    const int b0 = bb * RCHUNK;
    const int b1 = min(b0 + RCHUNK, A_GRID);
    for (int b = b0; b < b1; b++) s += g_part_sums[b * (K * D) + e];
    g_mid[bb * (K * D) + e] = s;
}

// ============================================================================
// Kernel 3: final reduce + prototype EMA update + renormalize (1 block)
// ============================================================================
__global__ void k_update(const float* __restrict__ protos)
{
    __shared__ float s_sums[K * D];
    __shared__ int   s_cnt[K];

    const int tid  = threadIdx.x;
    const int lane = tid & 31;
    const int warp = tid >> 5;

    for (int e = tid; e < K * D; e += 256) {
        float s = 0.0f;
#pragma unroll
        for (int m = 0; m < 8; m++) s += g_mid[m * (K * D) + e];
        s_sums[e] = s;
    }
    {
        int c = 0;
        for (int b = lane; b < A_GRID; b += 32) c += g_part_counts[b * K + warp];
        c = __reduce_add_sync(FULLM, c);
        if (lane == 0) s_cnt[warp] = c;
    }
    __syncthreads();

    const int k = warp;
    const float4* s4 = (const float4*)s_sums;
    float4 s1 = s4[k * 64 + lane];
    float4 s2 = s4[k * 64 + 32 + lane];

    const int   c = s_cnt[k];
    const float rr = 1.0f / fmaxf((float)c, 1.0f);
    float4 m1 = make_float4(s1.x*rr, s1.y*rr, s1.z*rr, s1.w*rr);
    float4 m2 = make_float4(s2.x*rr, s2.y*rr, s2.z*rr, s2.w*rr);

    float ss = m1.x*m1.x + m1.y*m1.y + m1.z*m1.z + m1.w*m1.w
             + m2.x*m2.x + m2.y*m2.y + m2.z*m2.z + m2.w*m2.w;
    ss = warp_sum(ss);
    const float inv = 1.0f / fmaxf(sqrtf(ss), 1e-12f);

    const float4* p4 = (const float4*)protos;
    const float4 p1 = p4[k * 64 + lane];
    const float4 p2 = p4[k * 64 + 32 + lane];

    float4 u1, u2;
    if (c > 0) {
        u1 = make_float4(0.9f*p1.x + 0.1f*m1.x*inv, 0.9f*p1.y + 0.1f*m1.y*inv,
                         0.9f*p1.z + 0.1f*m1.z*inv, 0.9f*p1.w + 0.1f*m1.w*inv);
        u2 = make_float4(0.9f*p2.x + 0.1f*m2.x*inv, 0.9f*p2.y + 0.1f*m2.y*inv,
                         0.9f*p2.z + 0.1f*m2.z*inv, 0.9f*p2.w + 0.1f*m2.w*inv);
    } else {
        u1 = p1; u2 = p2;
    }

    float ss2 = u1.x*u1.x + u1.y*u1.y + u1.z*u1.z + u1.w*u1.w
              + u2.x*u2.x + u2.y*u2.y + u2.z*u2.z + u2.w*u2.w;
    ss2 = warp_sum(ss2);
    const float inv2 = 1.0f / fmaxf(sqrtf(ss2), 1e-12f);

    float4* o4 = (float4*)g_protos_new;
    o4[k * 64 + lane]      = make_float4(u1.x*inv2, u1.y*inv2, u1.z*inv2, u1.w*inv2);
    o4[k * 64 + 32 + lane] = make_float4(u2.x*inv2, u2.y*inv2, u2.z*inv2, u2.w*inv2);
}

// ============================================================================
// Kernel 4 (NEW): target loss via tf32 MMA. One warp = 16-row tile.
// cp.async 4-quarter ring (depth 2), dots from tensor pipe, norms fp32 exact.
// ============================================================================
__global__ void __launch_bounds__(L_TPB, 5)
k_loss(const float* __restrict__ tgt, int N)
{
    __shared__ float s_p[K * PITCH];              // padded protos: 8.32 KB
    __shared__ float s_tile[2][16 * PITCH];       // per-warp tile: 16.64 KB each
    __shared__ float s_l[2];

    const int tid  = threadIdx.x;
    const int lane = tid & 31;
    const int warp = tid >> 5;
    const int g    = lane >> 2;   // 0..7
    const int t    = lane & 3;    // 0..3

    for (int e = tid; e < K * PITCH; e += L_TPB) {
        int k = e / PITCH, c = e - k * PITCH;
        s_p[e] = (c < D) ? g_protos_new[k * D + c] : 0.0f;
    }
    __syncthreads();

    const int gw     = blockIdx.x * 2 + warp;
    const int ntiles = (N + 15) >> 4;
    const int own    = (gw < ntiles) ? ((ntiles - 1 - gw) / L_TOTW + 1) : 0;
    const int Jmax   = own * 4;

    float* tile = s_tile[warp];
    const uint32_t tbase = (uint32_t)__cvta_generic_to_shared(tile);

    auto issue = [&](int j) {
        const int slot = j & 3;
        int jd = (j < Jmax) ? j : (Jmax - 1);
        const int tt = gw + (jd >> 2) * L_TOTW;
        const int q  = jd & 3;
        const int row0 = tt << 4;
#pragma unroll
        for (int i = 0; i < 8; i++) {
            int u = i * 32 + lane;
            int r = u >> 4, c = u & 15;
            int row = row0 + r; if (row >= N) row = N - 1;
            cp16(tbase + (uint32_t)(r * PITCH + slot * 64 + c * 4) * 4,
                 tgt + (size_t)row * D + q * 64 + c * 4);
        }
        asm volatile("cp.async.commit_group;" ::: "memory");
    };

    float lsum = 0.0f;
    float c0 = 0.f, c1 = 0.f, c2 = 0.f, c3 = 0.f, ssg = 0.f, ssh = 0.f;

    if (Jmax > 0) { issue(0); issue(1); }

    for (int j = 0; j < Jmax; j++) {
        asm volatile("cp.async.wait_group 1;" ::: "memory");
        __syncwarp();
        issue(j + 2);

        const int q = j & 3;
        const float* A0 = tile + g * PITCH + q * 64 + t;
        const float* A1 = tile + (g + 8) * PITCH + q * 64 + t;
        const float* Bp = s_p + g * PITCH + q * 64 + t;

#pragma unroll
        for (int s = 0; s < 16; s++) {
            float a0 = A0[s * 4];
            float a1 = A1[s * 4];
            float bb = Bp[s * 4];
            ssg = fmaf(a0, a0, ssg);
            ssh = fmaf(a1, a1, ssh);
            uint32_t ua0 = __float_as_uint(a0);
            uint32_t ua1 = __float_as_uint(a1);
            uint32_t ub  = __float_as_uint(bb);
            asm volatile(
                "mma.sync.aligned.m16n8k4.row.col.f32.tf32.tf32.f32 "
                "{%0,%1,%2,%3}, {%4,%5}, {%6}, {%0,%1,%2,%3};"
                : "+f"(c0), "+f"(c1), "+f"(c2), "+f"(c3)
                : "r"(ua0), "r"(ua1), "r"(ub));
        }

        if (q == 3) {
            // norms: lane covers 64 cols of rows g / g+8; reduce over 4-lane group
            ssg += __shfl_xor_sync(FULLM, ssg, 1);
            ssg += __shfl_xor_sync(FULLM, ssg, 2);
            ssh += __shfl_xor_sync(FULLM, ssh, 1);
            ssh += __shfl_xor_sync(FULLM, ssh, 2);
            // max over 8 proto cols: thread-pair fmax + 2 shfl-max
            float m0 = fmaxf(c0, c1);
            float m1 = fmaxf(c2, c3);
            m0 = fmaxf(m0, __shfl_xor_sync(FULLM, m0, 1));
            m0 = fmaxf(m0, __shfl_xor_sync(FULLM, m0, 2));
            m1 = fmaxf(m1, __shfl_xor_sync(FULLM, m1, 1));
            m1 = fmaxf(m1, __shfl_xor_sync(FULLM, m1, 2));

            const int tt = gw + (j >> 2) * L_TOTW;
            const int row0 = tt << 4;
            if (t == 0) {
                if (row0 + g < N)     lsum += m0 * rsqrtf(fmaxf(ssg, 1e-24f));
                if (row0 + 8 + g < N) lsum += m1 * rsqrtf(fmaxf(ssh, 1e-24f));
            }
            c0 = c1 = c2 = c3 = 0.f;
            ssg = ssh = 0.f;
        }
    }

    lsum = warp_sum(lsum);
    if (lane == 0) s_l[warp] = lsum;
    __syncthreads();
    if (tid == 0) g_part_loss[blockIdx.x] = s_l[0] + s_l[1];
}

// ============================================================================
// Kernel 5: final mean:  out = 1 - (sum of max cos) / Nt
// ============================================================================
__global__ void k_final(float* __restrict__ out, int Nt)
{
    __shared__ float sw[16];
    const int tid  = threadIdx.x;
    const int lane = tid & 31;
    const int warp = tid >> 5;

    float v = 0.0f;
    for (int i = tid; i < L_CTAS; i += 512) v += g_part_loss[i];
    v = warp_sum(v);
    if (lane == 0) sw[warp] = v;
    __syncthreads();
    if (tid == 0) {
        float s = 0.0f;
#pragma unroll
        for (int w = 0; w < 16; w++) s += sw[w];
        out[0] = 1.0f - s / (float)Nt;
    }
}

// ============================================================================
extern "C" void kernel_launch(void* const* d_in, const int* in_sizes, int n_in,
                              void* d_out, int out_size)
{
    const float* src    = (const float*)d_in[0];
    const float* tgt    = (const float*)d_in[1];
    const float* protos = (const float*)d_in[2];
    float* out = (float*)d_out;

    const int Ns = in_sizes[0] / D;
    const int Nt = in_sizes[1] / D;

    k_assign<<<A_GRID, A_TPB>>>(src, protos, Ns);
    k_reduce1<<<64, 256>>>();
    k_update<<<1, 256>>>(protos);
    k_loss<<<L_CTAS, L_TPB>>>(tgt, Nt);
    k_final<<<1, 512>>>(out, Nt);
}